// round 6
// baseline (speedup 1.0000x reference)
#include <cuda_runtime.h>
#include <cuda_bf16.h>
#include <cuda_fp8.h>
#include <cstdint>

// ============================================================================
// Problem constants — inputs and output are FLOAT32 buffers (bf16 values
// materialized as f32 by the harness; output compared as f32 of bf16 values)
// ============================================================================
static constexpr int K_DIM = 2048;
static constexpr int N_DIM = 2048;
static constexpr int M_MAX = 8192;

// fp8 scratch + scalars (device globals — no allocation allowed)
__device__ __align__(128) unsigned char g_x_fp8[(size_t)M_MAX * K_DIM];  // 16 MB
__device__ __align__(128) unsigned char g_w_fp8[(size_t)N_DIM * K_DIM]; //  4 MB
__device__ unsigned int g_amax_bits[2];   // [0]=x, [1]=w
__device__ float        g_scale[2];       // per-tensor scale
__device__ float        g_scale_comb;     // sx*sw for epilogue

__device__ __forceinline__ uint32_t smem_to_u32(const void* smem_ptr) {
    uint32_t addr;
    asm("{ .reg .u64 tmp; cvta.to.shared.u64 tmp, %1; cvt.u32.u64 %0, tmp; }"
        : "=r"(addr) : "l"(smem_ptr));
    return addr;
}

#define CP_ASYNC16(dst, src) \
    asm volatile("cp.async.cg.shared.global [%0], [%1], 16;" :: "r"(dst), "l"(src) : "memory")
#define CP_ASYNC_COMMIT() asm volatile("cp.async.commit_group;" ::: "memory")
#define CP_ASYNC_WAIT2()  asm volatile("cp.async.wait_group 2;" ::: "memory")

#define LDMATRIX_X4(r0, r1, r2, r3, addr) \
    asm volatile("ldmatrix.sync.aligned.m8n8.x4.shared.b16 {%0,%1,%2,%3}, [%4];" \
                 : "=r"(r0), "=r"(r1), "=r"(r2), "=r"(r3) : "r"(addr))

#define MMA_E4M3(c0, c1, c2, c3, a0, a1, a2, a3, b0, b1) \
    asm volatile("mma.sync.aligned.m16n8k32.row.col.f32.e4m3.e4m3.f32 " \
                 "{%0,%1,%2,%3}, {%4,%5,%6,%7}, {%8,%9}, {%0,%1,%2,%3};" \
                 : "+f"(c0), "+f"(c1), "+f"(c2), "+f"(c3) \
                 : "r"(a0), "r"(a1), "r"(a2), "r"(a3), "r"(b0), "r"(b1))

// ============================================================================
// Kernel 0: reset amax accumulators (graph replayed N times — must reset)
// ============================================================================
__global__ void init_kernel() {
    g_amax_bits[0] = 0u;
    g_amax_bits[1] = 0u;
}

// ============================================================================
// Kernel 1: amax over |f32| (values are exact bf16 images — max is exact)
// ============================================================================
__global__ void amax_kernel(const float* __restrict__ in, size_t n4, int which) {
    const float4* p = reinterpret_cast<const float4*>(in);
    float m = 0.0f;
    size_t i = (size_t)blockIdx.x * blockDim.x + threadIdx.x;
    size_t stride = (size_t)gridDim.x * blockDim.x;
    for (; i < n4; i += stride) {
        float4 v = p[i];
        m = fmaxf(m, fmaxf(fmaxf(fabsf(v.x), fabsf(v.y)),
                           fmaxf(fabsf(v.z), fabsf(v.w))));
    }
    #pragma unroll
    for (int o = 16; o > 0; o >>= 1)
        m = fmaxf(m, __shfl_xor_sync(0xFFFFFFFFu, m, o));
    __shared__ float smax[8];
    int wid = threadIdx.x >> 5, lid = threadIdx.x & 31;
    if (lid == 0) smax[wid] = m;
    __syncthreads();
    if (wid == 0) {
        m = (lid < (int)(blockDim.x >> 5)) ? smax[lid] : 0.0f;
        #pragma unroll
        for (int o = 4; o > 0; o >>= 1)
            m = fmaxf(m, __shfl_xor_sync(0xFFFFFFFFu, m, o));
        if (lid == 0)
            atomicMax(&g_amax_bits[which], __float_as_uint(m));  // positive floats: uint order == float order
    }
}

// ============================================================================
// Kernel 2: scales
// ============================================================================
__global__ void scales_kernel() {
    float ax = __uint_as_float(g_amax_bits[0]);
    float aw = __uint_as_float(g_amax_bits[1]);
    float sx = fmaxf(__fdiv_rn(ax, 448.0f), 1e-12f);
    float sw = fmaxf(__fdiv_rn(aw, 448.0f), 1e-12f);
    g_scale[0] = sx;
    g_scale[1] = sw;
    g_scale_comb = sx * sw;
}

// ============================================================================
// Kernel 3: quantize f32 -> e4m3 (exact f32 division, RNE satfinite)
//   8 elements per iteration: two float4 loads -> 8 fp8 bytes (uint2 store)
// ============================================================================
__global__ void quant_kernel(const float* __restrict__ in,
                             unsigned char* __restrict__ outp, size_t n8, int which) {
    float s = g_scale[which];
    const float4* p = reinterpret_cast<const float4*>(in);
    uint2* q = reinterpret_cast<uint2*>(outp);
    size_t i = (size_t)blockIdx.x * blockDim.x + threadIdx.x;
    size_t stride = (size_t)gridDim.x * blockDim.x;
    for (; i < n8; i += stride) {
        float4 v0 = p[2 * i];
        float4 v1 = p[2 * i + 1];
        float2 f0 = make_float2(__fdiv_rn(v0.x, s), __fdiv_rn(v0.y, s));
        float2 f1 = make_float2(__fdiv_rn(v0.z, s), __fdiv_rn(v0.w, s));
        float2 f2 = make_float2(__fdiv_rn(v1.x, s), __fdiv_rn(v1.y, s));
        float2 f3 = make_float2(__fdiv_rn(v1.z, s), __fdiv_rn(v1.w, s));
        uint32_t b0 = __nv_cvt_float2_to_fp8x2(f0, __NV_SATFINITE, __NV_E4M3);
        uint32_t b1 = __nv_cvt_float2_to_fp8x2(f1, __NV_SATFINITE, __NV_E4M3);
        uint32_t b2 = __nv_cvt_float2_to_fp8x2(f2, __NV_SATFINITE, __NV_E4M3);
        uint32_t b3 = __nv_cvt_float2_to_fp8x2(f3, __NV_SATFINITE, __NV_E4M3);
        uint2 r;
        r.x = (b0 & 0xFFFFu) | (b1 << 16);
        r.y = (b2 & 0xFFFFu) | (b3 << 16);
        q[i] = r;
    }
}

// ============================================================================
// Kernel 4: FP8 GEMM via mma.sync.m16n8k32 e4m3 (base-arch path)
//   out[m,n] = f32(bf16(sc * sum_k A[m,k]*B[n,k]))
//   A = g_x_fp8 [M,K], B = g_w_fp8 [N,K] (K-major)
//   CTA tile 128x128, BK=64 bytes, 4-stage cp.async, 256 threads.
//   Warp grid 2(M) x 4(N): warp tile 64x32.
// ============================================================================
static constexpr int BM = 128, BN = 128, BK = 64;
static constexpr int STAGES = 4;
static constexpr int PITCH = 80;                    // bytes/row: conflict-free
static constexpr int TILE_A = BM * PITCH;           // 10240 bytes
static constexpr int STAGE_B = 2 * TILE_A;          // 20480 bytes per stage
static constexpr int GEMM_SMEM = STAGES * STAGE_B;  // 81920 bytes
static constexpr int KITERS = K_DIM / BK;           // 32

__device__ __forceinline__ void load_stage(
    const uint8_t* __restrict__ Aq, const uint8_t* __restrict__ Bq,
    uint32_t sbase, int ki, int m0, int n0, int tid)
{
    uint32_t sdst = sbase + (ki % STAGES) * STAGE_B;
    int kb = ki * BK;
    #pragma unroll
    for (int p = 0; p < 4; p++) {
        int id  = p * 256 + tid;
        int rid = id & 511;
        int row = rid >> 2;
        int ch  = rid & 3;
        const uint8_t* src;
        uint32_t dst;
        if (p < 2) {  // A chunks
            src = Aq + (size_t)(m0 + row) * K_DIM + kb + ch * 16;
            dst = sdst + row * PITCH + ch * 16;
        } else {      // B chunks
            src = Bq + (size_t)(n0 + row) * K_DIM + kb + ch * 16;
            dst = sdst + TILE_A + row * PITCH + ch * 16;
        }
        CP_ASYNC16(dst, src);
    }
}

__global__ void __launch_bounds__(256, 2) gemm_kernel(
    const uint8_t* __restrict__ Aq, const uint8_t* __restrict__ Bq,
    float* __restrict__ out)
{
    extern __shared__ char smem[];
    uint32_t sbase = smem_to_u32(smem);
    int tid  = threadIdx.x;
    int lane = tid & 31;
    int wid  = tid >> 5;
    int warp_m = wid & 1;   // 0..1
    int warp_n = wid >> 1;  // 0..3
    int m0 = blockIdx.x * BM;
    int n0 = blockIdx.y * BN;

    float c[4][4][4];
    #pragma unroll
    for (int mf = 0; mf < 4; mf++)
        #pragma unroll
        for (int nf = 0; nf < 4; nf++)
            #pragma unroll
            for (int e = 0; e < 4; e++) c[mf][nf][e] = 0.0f;

    #pragma unroll
    for (int ki = 0; ki < STAGES - 1; ki++) {
        load_stage(Aq, Bq, sbase, ki, m0, n0, tid);
        CP_ASYNC_COMMIT();
    }

    int frow = lane & 15;   // row within 16-row fragment
    int fch  = lane >> 4;   // 16-byte chunk select

    for (int ki = 0; ki < KITERS; ki++) {
        CP_ASYNC_WAIT2();
        __syncthreads();

        if (ki + STAGES - 1 < KITERS)
            load_stage(Aq, Bq, sbase, ki + STAGES - 1, m0, n0, tid);
        CP_ASYNC_COMMIT();

        uint32_t sA = sbase + (ki % STAGES) * STAGE_B;
        uint32_t sB = sA + TILE_A;

        #pragma unroll
        for (int ks = 0; ks < 2; ks++) {          // kk = ks*32
            int cbase = (ks << 1) + fch;          // 16B-chunk index 0..3
            uint32_t aAddr = sA + (warp_m * 64 + frow) * PITCH + cbase * 16;
            uint32_t bAddr = sB + (warp_n * 32 + frow) * PITCH + cbase * 16;

            uint32_t a[4][4];
            #pragma unroll
            for (int mf = 0; mf < 4; mf++)
                LDMATRIX_X4(a[mf][0], a[mf][1], a[mf][2], a[mf][3],
                            aAddr + mf * 16 * PITCH);

            uint32_t b[4][2];
            #pragma unroll
            for (int nfp = 0; nfp < 2; nfp++) {
                uint32_t r0, r1, r2, r3;
                LDMATRIX_X4(r0, r1, r2, r3, bAddr + nfp * 16 * PITCH);
                b[2 * nfp][0]     = r0;  b[2 * nfp][1]     = r2;  // n rows 0-7
                b[2 * nfp + 1][0] = r1;  b[2 * nfp + 1][1] = r3;  // n rows 8-15
            }

            #pragma unroll
            for (int mf = 0; mf < 4; mf++)
                #pragma unroll
                for (int nf = 0; nf < 4; nf++)
                    MMA_E4M3(c[mf][nf][0], c[mf][nf][1], c[mf][nf][2], c[mf][nf][3],
                             a[mf][0], a[mf][1], a[mf][2], a[mf][3],
                             b[nf][0], b[nf][1]);
        }
        __syncthreads();
    }

    // epilogue: scale, round to bf16 (reference casts to bf16), store as f32
    float sc = g_scale_comb;
    int r  = lane >> 2;
    int cq = (lane & 3) * 2;
    #pragma unroll
    for (int mf = 0; mf < 4; mf++) {
        #pragma unroll
        for (int nf = 0; nf < 4; nf++) {
            int gm = m0 + warp_m * 64 + mf * 16 + r;
            int gn = n0 + warp_n * 32 + nf * 8 + cq;
            float2 e0, e1;
            e0.x = __bfloat162float(__float2bfloat16_rn(c[mf][nf][0] * sc));
            e0.y = __bfloat162float(__float2bfloat16_rn(c[mf][nf][1] * sc));
            e1.x = __bfloat162float(__float2bfloat16_rn(c[mf][nf][2] * sc));
            e1.y = __bfloat162float(__float2bfloat16_rn(c[mf][nf][3] * sc));
            *reinterpret_cast<float2*>(out + (size_t)gm * N_DIM + gn) = e0;
            *reinterpret_cast<float2*>(out + (size_t)(gm + 8) * N_DIM + gn) = e1;
        }
    }
}

// ============================================================================
// Host launcher
// ============================================================================
extern "C" void kernel_launch(void* const* d_in, const int* in_sizes, int n_in,
                              void* d_out, int out_size) {
    // x is the larger tensor, weight the smaller
    int ix = 0, iw = 1;
    if (n_in >= 2 && in_sizes[1] > in_sizes[0]) { ix = 1; iw = 0; }
    const float* x = (const float*)d_in[ix];
    const float* w = (const float*)d_in[iw];
    float* out = (float*)d_out;

    size_t nx = (size_t)in_sizes[ix];   // 16,777,216
    size_t nw = (size_t)in_sizes[iw];   //  4,194,304
    int M = (int)(nx / K_DIM);          // 8192

    void *xq = nullptr, *wq = nullptr;
    cudaGetSymbolAddress(&xq, g_x_fp8);
    cudaGetSymbolAddress(&wq, g_w_fp8);

    init_kernel<<<1, 1>>>();
    amax_kernel<<<2048, 256>>>(x, nx / 4, 0);
    amax_kernel<<<1024, 256>>>(w, nw / 4, 1);
    scales_kernel<<<1, 1>>>();
    quant_kernel<<<2048, 256>>>(x, (unsigned char*)xq, nx / 8, 0);
    quant_kernel<<<1024, 256>>>(w, (unsigned char*)wq, nw / 8, 1);

    cudaFuncSetAttribute(gemm_kernel, cudaFuncAttributeMaxDynamicSharedMemorySize, GEMM_SMEM);
    dim3 grid(M / BM, N_DIM / BN);
    gemm_kernel<<<grid, 256, GEMM_SMEM>>>((const uint8_t*)xq, (const uint8_t*)wq, out);
}